// round 8
// baseline (speedup 1.0000x reference)
#include <cuda_runtime.h>
#include <cstdint>

#define TS   16
#define NT   512
#define NBLK 128

__constant__ int c_FOFF[9] = {0,100000,150000,150010,150013,150113,150163,151163,151187};
__constant__ int c_EDIM[9] = {16,16,8,4,8,8,8,4,4};
__constant__ int c_EOFF[9] = {0,16,32,40,44,52,60,68,72};
#define NF_LAST 151192

struct P30 { const void* p[30]; };
typedef unsigned long long u64;

// ---- weight scratch: (hi,lo) tf32 pairs, built by prep kernel each launch ----
__device__ uint2 g_W1p[80 * 256];    // K padded 77->80
__device__ uint2 g_W2p[256 * 128];

__device__ __forceinline__ void ffma2(u64 &d, u64 a, u64 b) {
    asm("fma.rn.f32x2 %0, %1, %2, %0;" : "+l"(d) : "l"(a), "l"(b));
}
__device__ __forceinline__ void fadd2(u64 &d, u64 a) {
    asm("add.rn.f32x2 %0, %0, %1;" : "+l"(d) : "l"(a));
}
__device__ __forceinline__ u64 pack2(float x) {
    u64 r; asm("mov.b64 %0, {%1, %1};" : "=l"(r) : "f"(x)); return r;
}
__device__ __forceinline__ float2 unpack2(u64 v) {
    float2 f; asm("mov.b64 {%0, %1}, %2;" : "=f"(f.x), "=f"(f.y) : "l"(v)); return f;
}
__device__ __forceinline__ u64 d2u(double d) { return __double_as_longlong(d); }
__device__ __forceinline__ int read_id(const void* p, int i, bool is64) {
    return is64 ? (int)((const long long*)p)[i] : ((const int*)p)[i];
}
__device__ __forceinline__ unsigned f2tf(float v) {
    unsigned r; asm("cvt.rna.tf32.f32 %0, %1;" : "=r"(r) : "f"(v)); return r;
}
__device__ __forceinline__ uint2 mk_hl(float v) {
    unsigned h = f2tf(v);
    float lo = v - __uint_as_float(h);
    return make_uint2(h, f2tf(lo));
}
__device__ __forceinline__ void mma8(float &c0, float &c1, float &c2, float &c3,
                                     unsigned a0, unsigned a1, unsigned a2, unsigned a3,
                                     unsigned b0, unsigned b1) {
    asm("mma.sync.aligned.m16n8k8.row.col.f32.tf32.tf32.f32 "
        "{%0,%1,%2,%3}, {%4,%5,%6,%7}, {%8,%9}, {%0,%1,%2,%3};"
        : "+f"(c0), "+f"(c1), "+f"(c2), "+f"(c3)
        : "r"(a0), "r"(a1), "r"(a2), "r"(a3), "r"(b0), "r"(b1));
}

// ---- prep kernel: fp32 weights -> (hi,lo) tf32 scratch ----
extern "C" __global__ void prep_kernel(const float* __restrict__ W1,
                                       const float* __restrict__ W2)
{
    int i = blockIdx.x * blockDim.x + threadIdx.x;
    if (i < 80 * 256) {
        int k = i >> 8, n = i & 255;
        float v = (k < 77) ? W1[k * 256 + n] : 0.f;
        g_W1p[i] = mk_hl(v);
    } else if (i < 80 * 256 + 256 * 128) {
        int m = i - 80 * 256;
        g_W2p[m] = mk_hl(W2[m]);
    }
}

// smem byte offsets
#define OFF_XHL   0                        // uint2[16][84]  (stride words 168 ≡ 8 mod 32)
#define OFF_H1HL  10752                    // uint2[16][260] (stride words 520 ≡ 8 mod 32)
#define OFF_H2T   44032                    // float[128][20]
#define OFF_H3T   54272                    // float[64][20]
#define OFF_BASE  59392                    // float[16]
#define OFF_PRICE 59456                    // float[16]
#define OFF_IDX   59520                    // int[144]
#define SMEM_BYTES 60096

extern "C" __global__ void __launch_bounds__(NT, 1)
deepfm_kernel(P30 a, float* __restrict__ out, int B)
{
    extern __shared__ __align__(16) char smem[];
    uint2* sXhl   = (uint2*)(smem + OFF_XHL);
    uint2* sH1hl  = (uint2*)(smem + OFF_H1HL);
    float* sH2T   = (float*)(smem + OFF_H2T);
    float* sH3T   = (float*)(smem + OFF_H3T);
    float* sBase  = (float*)(smem + OFF_BASE);
    float* sPrice = (float*)(smem + OFF_PRICE);
    int*   sIdx   = (int*)  (smem + OFF_IDX);

    const int t  = threadIdx.x;
    const int w  = t >> 5;
    const int ln = t & 31;
    const int gid = ln >> 2;     // MMA group id (row)
    const int tig = ln & 3;      // MMA thread-in-group (col)
    const int s0blk = blockIdx.x * TS;

    // ---- input-layout detection ----
    const u64* u0 = (const u64*)a.p[0];
    const bool is64 = ((u0[0] | u0[1] | u0[2] | u0[3]) < (1ULL << 20));
    const u64* u7 = (const u64*)a.p[7];
    const bool dict = (u7[0] < (1ULL << 40));

    const void* idp[9];
    #pragma unroll
    for (int f = 0; f < 7; f++) idp[f] = a.p[f];
    const float* price;
    if (dict) { idp[7] = a.p[7]; idp[8] = a.p[8]; price = (const float*)a.p[9]; }
    else      { price = (const float*)a.p[7]; idp[7] = a.p[8]; idp[8] = a.p[9]; }

    const float* emb[9];
    #pragma unroll
    for (int f = 0; f < 9; f++) emb[f] = (const float*)a.p[10 + f];
    const float* __restrict__ w_dense = (const float*)a.p[19];
    const float* __restrict__ b_dense = (const float*)a.p[20];
    const float* __restrict__ fm_v    = (const float*)a.p[21];
    const float* __restrict__ b1 = (const float*)a.p[23];
    const float* __restrict__ b2 = (const float*)a.p[25];
    const float* __restrict__ W3 = (const float*)a.p[26];
    const float* __restrict__ b3 = (const float*)a.p[27];
    const float* __restrict__ Wo = (const float*)a.p[28];
    const float* __restrict__ bo = (const float*)a.p[29];

    // ---- gather ids + price ----
    if (t < TS * 9) {
        int s = t / 9, f = t - s * 9;
        sIdx[s * 9 + f] = read_id(idp[f], s0blk + s, is64);
    }
    if (t >= 160 && t < 160 + TS) sPrice[t - 160] = price[s0blk + (t - 160)];
    __syncthreads();

    // ---- warps 0-7: FM + dense; warps 8-15: build X (hi,lo) [16][84] ----
    if (w < 8) {
        int s = w * 2 + (ln >> 4);
        int e = ln & 15;
        float pv = sPrice[s] * 1e-3f;
        float fs = 0.f, ss = 0.f;
        #pragma unroll
        for (int f = 0; f < 9; f++) {
            int row = c_FOFF[f] + sIdx[s * 9 + f];
            float v = fm_v[row * 16 + e];
            fs += v; ss += v * v;
        }
        {
            float v = fm_v[NF_LAST * 16 + e];
            fs += pv * v; ss += pv * pv * v * v;
        }
        float val = fs * fs - ss;
        #pragma unroll
        for (int o = 8; o; o >>= 1) val += __shfl_xor_sync(0xffffffffu, val, o, 16);
        float fm = 0.5f * val;

        float dn = 0.f;
        if (e < 9)  dn = w_dense[c_FOFF[e] + sIdx[s * 9 + e]];
        if (e == 9) dn = pv * w_dense[NF_LAST];
        #pragma unroll
        for (int o = 8; o; o >>= 1) dn += __shfl_xor_sync(0xffffffffu, dn, o, 16);

        if (e == 0) sBase[s] = fm + dn + b_dense[0];
    } else {
        for (int idx = t - 256; idx < TS * 80; idx += 256) {
            int s = idx & 15, c = idx >> 4;
            float v = 0.f;
            if (c == 76) v = sPrice[s];
            else if (c < 76) {
                int f = 8;
                #pragma unroll
                for (int k = 8; k >= 1; k--) if (c < c_EOFF[k]) f = k - 1;
                v = emb[f][sIdx[s * 9 + f] * c_EDIM[f] + (c - c_EOFF[f])];
            }
            sXhl[s * 84 + c] = mk_hl(v);
        }
    }
    __syncthreads();

    // ---- Layer 1 (tensor): H1 = relu(X @ W1 + b1). M=16, N=256, K=80. ----
    // warp w -> n-tiles {2w, 2w+1} (n0 = 16w). 10 k-steps, 3xTF32.
    {
        const int n0 = w * 16;
        float c0[4] = {0,0,0,0}, c1[4] = {0,0,0,0};
        const uint2* pA = sXhl + gid * 84 + tig;
        #pragma unroll
        for (int ks = 0; ks < 10; ks++) {
            int k0 = ks * 8;
            uint2 A0 = pA[k0];
            uint2 A1 = pA[8 * 84 + k0];
            uint2 A2 = pA[k0 + 4];
            uint2 A3 = pA[8 * 84 + k0 + 4];
            uint2 B0a = g_W1p[(k0 + tig) * 256 + n0 + gid];
            uint2 B1a = g_W1p[(k0 + 4 + tig) * 256 + n0 + gid];
            uint2 B0b = g_W1p[(k0 + tig) * 256 + n0 + 8 + gid];
            uint2 B1b = g_W1p[(k0 + 4 + tig) * 256 + n0 + 8 + gid];
            mma8(c0[0],c0[1],c0[2],c0[3], A0.x,A1.x,A2.x,A3.x, B0a.x,B1a.x);
            mma8(c0[0],c0[1],c0[2],c0[3], A0.x,A1.x,A2.x,A3.x, B0a.y,B1a.y);
            mma8(c0[0],c0[1],c0[2],c0[3], A0.y,A1.y,A2.y,A3.y, B0a.x,B1a.x);
            mma8(c1[0],c1[1],c1[2],c1[3], A0.x,A1.x,A2.x,A3.x, B0b.x,B1b.x);
            mma8(c1[0],c1[1],c1[2],c1[3], A0.x,A1.x,A2.x,A3.x, B0b.y,B1b.y);
            mma8(c1[0],c1[1],c1[2],c1[3], A0.y,A1.y,A2.y,A3.y, B0b.x,B1b.x);
        }
        // epilogue: bias + relu -> (hi,lo) into sH1hl[m][n]
        #pragma unroll
        for (int nt = 0; nt < 2; nt++) {
            float* c = nt ? c1 : c0;
            int nb = n0 + nt * 8 + 2 * tig;
            float2 bv = *(const float2*)(b1 + nb);
            float v0 = fmaxf(c[0] + bv.x, 0.f);
            float v1 = fmaxf(c[1] + bv.y, 0.f);
            float v2 = fmaxf(c[2] + bv.x, 0.f);
            float v3 = fmaxf(c[3] + bv.y, 0.f);
            sH1hl[gid * 260 + nb]           = mk_hl(v0);
            sH1hl[gid * 260 + nb + 1]       = mk_hl(v1);
            sH1hl[(gid + 8) * 260 + nb]     = mk_hl(v2);
            sH1hl[(gid + 8) * 260 + nb + 1] = mk_hl(v3);
        }
    }
    __syncthreads();

    // ---- Layer 2 (tensor): H2 = relu(H1 @ W2 + b2). M=16, N=128, K=256. ----
    // warp w -> n-tile w (n0 = 8w). 32 k-steps, 3xTF32.
    {
        const int n0 = w * 8;
        float c0[4] = {0,0,0,0};
        const uint2* pA = sH1hl + gid * 260 + tig;
        #pragma unroll 8
        for (int ks = 0; ks < 32; ks++) {
            int k0 = ks * 8;
            uint2 A0 = pA[k0];
            uint2 A1 = pA[8 * 260 + k0];
            uint2 A2 = pA[k0 + 4];
            uint2 A3 = pA[8 * 260 + k0 + 4];
            uint2 B0 = g_W2p[(k0 + tig) * 128 + n0 + gid];
            uint2 B1 = g_W2p[(k0 + 4 + tig) * 128 + n0 + gid];
            mma8(c0[0],c0[1],c0[2],c0[3], A0.x,A1.x,A2.x,A3.x, B0.x,B1.x);
            mma8(c0[0],c0[1],c0[2],c0[3], A0.x,A1.x,A2.x,A3.x, B0.y,B1.y);
            mma8(c0[0],c0[1],c0[2],c0[3], A0.y,A1.y,A2.y,A3.y, B0.x,B1.x);
        }
        int nb = n0 + 2 * tig;
        float2 bv = *(const float2*)(b2 + nb);
        float v0 = fmaxf(c0[0] + bv.x, 0.f);
        float v1 = fmaxf(c0[1] + bv.y, 0.f);
        float v2 = fmaxf(c0[2] + bv.x, 0.f);
        float v3 = fmaxf(c0[3] + bv.y, 0.f);
        // transposed plain-float store for L3: sH2T[n][m]
        sH2T[nb * 20 + gid]           = v0;
        sH2T[(nb + 1) * 20 + gid]     = v1;
        sH2T[nb * 20 + gid + 8]       = v2;
        sH2T[(nb + 1) * 20 + gid + 8] = v3;
    }
    __syncthreads();

    // ---- Layer 3 (FFMA2): K=128 (intra-warp split x2), N=64. 16 warps x 4 j. ----
    {
        int jl = ln & 7, sg = ln >> 3;
        int j  = w * 4 + (jl >> 1);
        int kh = jl & 1;
        int s0 = sg * 4;
        u64 acc0 = 0, acc1 = 0;
        const float* Wp = W3 + kh * 64 * 64 + j;
        const float* Xp = sH2T + kh * 64 * 20 + s0;
        #pragma unroll 8
        for (int i = 0; i < 64; i++) {
            float wv = Wp[i * 64];
            double2 xv = *(const double2*)(Xp + i * 20);
            u64 wp = pack2(wv);
            ffma2(acc0, wp, d2u(xv.x));
            ffma2(acc1, wp, d2u(xv.y));
        }
        u64 r;
        r = __shfl_xor_sync(0xffffffffu, acc0, 1); fadd2(acc0, r);
        r = __shfl_xor_sync(0xffffffffu, acc1, 1); fadd2(acc1, r);
        if (kh == 0) {
            u64 bb = pack2(b3[j]);
            fadd2(acc0, bb); fadd2(acc1, bb);
            float2 f0 = unpack2(acc0), f1 = unpack2(acc1);
            *(float4*)(sH3T + j * 20 + s0) = make_float4(
                fmaxf(f0.x,0.f), fmaxf(f0.y,0.f), fmaxf(f1.x,0.f), fmaxf(f1.y,0.f));
        }
    }
    __syncthreads();

    // ---- Output: warps 0-3, 8 lanes per sample ----
    if (w < 4) {
        int s  = w * 4 + (ln >> 3);
        int q8 = ln & 7;
        float v = 0.f;
        #pragma unroll
        for (int q = 0; q < 8; q++)
            v += sH3T[(q8 * 8 + q) * 20 + s] * Wo[q8 * 8 + q];
        v += __shfl_xor_sync(0xffffffffu, v, 4, 8);
        v += __shfl_xor_sync(0xffffffffu, v, 2, 8);
        v += __shfl_xor_sync(0xffffffffu, v, 1, 8);
        if (q8 == 0 && s0blk + s < B)
            out[s0blk + s] = v + bo[0] + sBase[s];
    }
}

extern "C" void kernel_launch(void* const* d_in, const int* in_sizes, int n_in,
                              void* d_out, int out_size)
{
    (void)in_sizes; (void)n_in;
    P30 a;
    for (int i = 0; i < 30; i++) a.p[i] = d_in[i];
    prep_kernel<<<208, 256>>>((const float*)d_in[22], (const float*)d_in[24]);
    cudaFuncSetAttribute(deepfm_kernel, cudaFuncAttributeMaxDynamicSharedMemorySize, SMEM_BYTES);
    deepfm_kernel<<<NBLK, NT, SMEM_BYTES>>>(a, (float*)d_out, out_size);
}

// round 9
// speedup vs baseline: 1.0102x; 1.0102x over previous
#include <cuda_runtime.h>
#include <cstdint>

#define TS   16
#define NT   512
#define NBLK 128

__constant__ int c_FOFF[9] = {0,100000,150000,150010,150013,150113,150163,151163,151187};
__constant__ int c_EDIM[9] = {16,16,8,4,8,8,8,4,4};
__constant__ int c_EOFF[9] = {0,16,32,40,44,52,60,68,72};
#define NF_LAST 151192

struct P30 { const void* p[30]; };
typedef unsigned long long u64;

// ---- weight scratch: MMA-fragment-major (hi,lo) tf32, built by prep kernel ----
// W1f: ntile 0..31 (8 n each), kstep 0..9, lane word tig*8+gid
//      uint4{ hi(k0+tig,n), lo(k0+tig,n), hi(k0+4+tig,n), lo(k0+4+tig,n) }, n = nt*8+gid
__device__ uint4 g_W1f[32 * 10 * 32];   // 160 KB
__device__ uint4 g_W2f[16 * 32 * 32];   // 256 KB

__device__ __forceinline__ void ffma2(u64 &d, u64 a, u64 b) {
    asm("fma.rn.f32x2 %0, %1, %2, %0;" : "+l"(d) : "l"(a), "l"(b));
}
__device__ __forceinline__ void fadd2(u64 &d, u64 a) {
    asm("add.rn.f32x2 %0, %0, %1;" : "+l"(d) : "l"(a));
}
__device__ __forceinline__ u64 pack2(float x) {
    u64 r; asm("mov.b64 %0, {%1, %1};" : "=l"(r) : "f"(x)); return r;
}
__device__ __forceinline__ float2 unpack2(u64 v) {
    float2 f; asm("mov.b64 {%0, %1}, %2;" : "=f"(f.x), "=f"(f.y) : "l"(v)); return f;
}
__device__ __forceinline__ u64 d2u(double d) { return __double_as_longlong(d); }
__device__ __forceinline__ int read_id(const void* p, int i, bool is64) {
    return is64 ? (int)((const long long*)p)[i] : ((const int*)p)[i];
}
__device__ __forceinline__ unsigned f2tf(float v) {
    unsigned r; asm("cvt.rna.tf32.f32 %0, %1;" : "=r"(r) : "f"(v)); return r;
}
__device__ __forceinline__ uint2 mk_hl(float v) {
    unsigned h = f2tf(v);
    float lo = v - __uint_as_float(h);
    return make_uint2(h, f2tf(lo));
}
__device__ __forceinline__ void mma8(float &c0, float &c1, float &c2, float &c3,
                                     unsigned a0, unsigned a1, unsigned a2, unsigned a3,
                                     unsigned b0, unsigned b1) {
    asm("mma.sync.aligned.m16n8k8.row.col.f32.tf32.tf32.f32 "
        "{%0,%1,%2,%3}, {%4,%5,%6,%7}, {%8,%9}, {%0,%1,%2,%3};"
        : "+f"(c0), "+f"(c1), "+f"(c2), "+f"(c3)
        : "r"(a0), "r"(a1), "r"(a2), "r"(a3), "r"(b0), "r"(b1));
}

// ---- prep kernel: fp32 weights -> fragment-major (hi,lo) tf32 scratch ----
extern "C" __global__ void prep_kernel(const float* __restrict__ W1,
                                       const float* __restrict__ W2)
{
    int i = blockIdx.x * blockDim.x + threadIdx.x;
    if (i < 32 * 10 * 32) {               // W1f
        int gid = i & 7, tig = (i >> 3) & 3;
        int ks = (i >> 5) % 10, nt = i / 320;
        int n = nt * 8 + gid, k0 = ks * 8;
        int c0 = k0 + tig, c1 = k0 + 4 + tig;
        float v0 = (c0 < 77) ? W1[c0 * 256 + n] : 0.f;
        float v1 = (c1 < 77) ? W1[c1 * 256 + n] : 0.f;
        uint2 h0 = mk_hl(v0), h1 = mk_hl(v1);
        g_W1f[i] = make_uint4(h0.x, h0.y, h1.x, h1.y);
    } else if (i < 32 * 10 * 32 + 16 * 32 * 32) {   // W2f
        int m = i - 32 * 10 * 32;
        int gid = m & 7, tig = (m >> 3) & 3;
        int ks = (m >> 5) & 31, nt = m >> 10;
        int n = nt * 8 + gid, k0 = ks * 8;
        uint2 h0 = mk_hl(W2[(k0 + tig) * 128 + n]);
        uint2 h1 = mk_hl(W2[(k0 + 4 + tig) * 128 + n]);
        g_W2f[m] = make_uint4(h0.x, h0.y, h1.x, h1.y);
    }
}

// smem byte offsets
#define OFF_XHL   0                        // uint2[16][84]
#define OFF_H1HL  10752                    // uint2[16][260]
#define OFF_H2T   44032                    // float[128][20]
#define OFF_H3T   54272                    // float[64][20]
#define OFF_BASE  59392
#define OFF_PRICE 59456
#define OFF_IDX   59520
#define SMEM_BYTES 60096

extern "C" __global__ void __launch_bounds__(NT, 1)
deepfm_kernel(P30 a, float* __restrict__ out, int B)
{
    extern __shared__ __align__(16) char smem[];
    uint2* sXhl   = (uint2*)(smem + OFF_XHL);
    uint2* sH1hl  = (uint2*)(smem + OFF_H1HL);
    float* sH2T   = (float*)(smem + OFF_H2T);
    float* sH3T   = (float*)(smem + OFF_H3T);
    float* sBase  = (float*)(smem + OFF_BASE);
    float* sPrice = (float*)(smem + OFF_PRICE);
    int*   sIdx   = (int*)  (smem + OFF_IDX);

    const int t  = threadIdx.x;
    const int w  = t >> 5;
    const int ln = t & 31;
    const int gid = ln >> 2;
    const int tig = ln & 3;
    const int s0blk = blockIdx.x * TS;

    // ---- input-layout detection ----
    const u64* u0 = (const u64*)a.p[0];
    const bool is64 = ((u0[0] | u0[1] | u0[2] | u0[3]) < (1ULL << 20));
    const u64* u7 = (const u64*)a.p[7];
    const bool dict = (u7[0] < (1ULL << 40));

    const void* idp[9];
    #pragma unroll
    for (int f = 0; f < 7; f++) idp[f] = a.p[f];
    const float* price;
    if (dict) { idp[7] = a.p[7]; idp[8] = a.p[8]; price = (const float*)a.p[9]; }
    else      { price = (const float*)a.p[7]; idp[7] = a.p[8]; idp[8] = a.p[9]; }

    const float* emb[9];
    #pragma unroll
    for (int f = 0; f < 9; f++) emb[f] = (const float*)a.p[10 + f];
    const float* __restrict__ w_dense = (const float*)a.p[19];
    const float* __restrict__ b_dense = (const float*)a.p[20];
    const float* __restrict__ fm_v    = (const float*)a.p[21];
    const float* __restrict__ b1 = (const float*)a.p[23];
    const float* __restrict__ b2 = (const float*)a.p[25];
    const float* __restrict__ W3 = (const float*)a.p[26];
    const float* __restrict__ b3 = (const float*)a.p[27];
    const float* __restrict__ Wo = (const float*)a.p[28];
    const float* __restrict__ bo = (const float*)a.p[29];

    // ---- gather ids + price ----
    if (t < TS * 9) {
        int s = t / 9, f = t - s * 9;
        sIdx[s * 9 + f] = read_id(idp[f], s0blk + s, is64);
    }
    if (t >= 160 && t < 160 + TS) sPrice[t - 160] = price[s0blk + (t - 160)];
    __syncthreads();

    // ---- warps 0-7: FM + dense; warps 8-15: build X (hi,lo) [16][84] ----
    if (w < 8) {
        int s = w * 2 + (ln >> 4);
        int e = ln & 15;
        float pv = sPrice[s] * 1e-3f;
        float fs = 0.f, ss = 0.f;
        #pragma unroll
        for (int f = 0; f < 9; f++) {
            int row = c_FOFF[f] + sIdx[s * 9 + f];
            float v = fm_v[row * 16 + e];
            fs += v; ss += v * v;
        }
        {
            float v = fm_v[NF_LAST * 16 + e];
            fs += pv * v; ss += pv * pv * v * v;
        }
        float val = fs * fs - ss;
        #pragma unroll
        for (int o = 8; o; o >>= 1) val += __shfl_xor_sync(0xffffffffu, val, o, 16);
        float fm = 0.5f * val;

        float dn = 0.f;
        if (e < 9)  dn = w_dense[c_FOFF[e] + sIdx[s * 9 + e]];
        if (e == 9) dn = pv * w_dense[NF_LAST];
        #pragma unroll
        for (int o = 8; o; o >>= 1) dn += __shfl_xor_sync(0xffffffffu, dn, o, 16);

        if (e == 0) sBase[s] = fm + dn + b_dense[0];
    } else {
        for (int idx = t - 256; idx < TS * 80; idx += 256) {
            int s = idx & 15, c = idx >> 4;
            float v = 0.f;
            if (c == 76) v = sPrice[s];
            else if (c < 76) {
                int f = 8;
                #pragma unroll
                for (int k = 8; k >= 1; k--) if (c < c_EOFF[k]) f = k - 1;
                v = emb[f][sIdx[s * 9 + f] * c_EDIM[f] + (c - c_EOFF[f])];
            }
            sXhl[s * 84 + c] = mk_hl(v);
        }
    }
    __syncthreads();

    // ---- Layer 1 (tensor): M=16, N=256, K=80. warp w -> n-tiles {2w, 2w+1}. ----
    {
        float c0[4] = {0,0,0,0}, c1[4] = {0,0,0,0};
        const uint2* pA = sXhl + gid * 84 + tig;
        const uint4* pBa = g_W1f + (2 * w) * 320 + tig * 8 + gid;
        const uint4* pBb = g_W1f + (2 * w + 1) * 320 + tig * 8 + gid;
        #pragma unroll
        for (int ks = 0; ks < 10; ks++) {
            int k0 = ks * 8;
            uint2 A0 = pA[k0];
            uint2 A1 = pA[8 * 84 + k0];
            uint2 A2 = pA[k0 + 4];
            uint2 A3 = pA[8 * 84 + k0 + 4];
            uint4 Ba = pBa[ks * 32];
            uint4 Bb = pBb[ks * 32];
            mma8(c0[0],c0[1],c0[2],c0[3], A0.x,A1.x,A2.x,A3.x, Ba.x,Ba.z);
            mma8(c0[0],c0[1],c0[2],c0[3], A0.x,A1.x,A2.x,A3.x, Ba.y,Ba.w);
            mma8(c0[0],c0[1],c0[2],c0[3], A0.y,A1.y,A2.y,A3.y, Ba.x,Ba.z);
            mma8(c1[0],c1[1],c1[2],c1[3], A0.x,A1.x,A2.x,A3.x, Bb.x,Bb.z);
            mma8(c1[0],c1[1],c1[2],c1[3], A0.x,A1.x,A2.x,A3.x, Bb.y,Bb.w);
            mma8(c1[0],c1[1],c1[2],c1[3], A0.y,A1.y,A2.y,A3.y, Bb.x,Bb.z);
        }
        const int n0 = w * 16;
        #pragma unroll
        for (int nt = 0; nt < 2; nt++) {
            float* c = nt ? c1 : c0;
            int nb = n0 + nt * 8 + 2 * tig;
            float2 bv = *(const float2*)(b1 + nb);
            float v0 = fmaxf(c[0] + bv.x, 0.f);
            float v1 = fmaxf(c[1] + bv.y, 0.f);
            float v2 = fmaxf(c[2] + bv.x, 0.f);
            float v3 = fmaxf(c[3] + bv.y, 0.f);
            sH1hl[gid * 260 + nb]           = mk_hl(v0);
            sH1hl[gid * 260 + nb + 1]       = mk_hl(v1);
            sH1hl[(gid + 8) * 260 + nb]     = mk_hl(v2);
            sH1hl[(gid + 8) * 260 + nb + 1] = mk_hl(v3);
        }
    }
    __syncthreads();

    // ---- Layer 2 (tensor): M=16, N=128, K=256. warp w -> n-tile w. ----
    {
        float c0[4] = {0,0,0,0};
        const uint2* pA = sH1hl + gid * 260 + tig;
        const uint4* pB = g_W2f + w * 1024 + tig * 8 + gid;
        #pragma unroll 8
        for (int ks = 0; ks < 32; ks++) {
            int k0 = ks * 8;
            uint2 A0 = pA[k0];
            uint2 A1 = pA[8 * 260 + k0];
            uint2 A2 = pA[k0 + 4];
            uint2 A3 = pA[8 * 260 + k0 + 4];
            uint4 Bb = pB[ks * 32];
            mma8(c0[0],c0[1],c0[2],c0[3], A0.x,A1.x,A2.x,A3.x, Bb.x,Bb.z);
            mma8(c0[0],c0[1],c0[2],c0[3], A0.x,A1.x,A2.x,A3.x, Bb.y,Bb.w);
            mma8(c0[0],c0[1],c0[2],c0[3], A0.y,A1.y,A2.y,A3.y, Bb.x,Bb.z);
        }
        int nb = w * 8 + 2 * tig;
        float2 bv = *(const float2*)(b2 + nb);
        float v0 = fmaxf(c0[0] + bv.x, 0.f);
        float v1 = fmaxf(c0[1] + bv.y, 0.f);
        float v2 = fmaxf(c0[2] + bv.x, 0.f);
        float v3 = fmaxf(c0[3] + bv.y, 0.f);
        sH2T[nb * 20 + gid]           = v0;
        sH2T[(nb + 1) * 20 + gid]     = v1;
        sH2T[nb * 20 + gid + 8]       = v2;
        sH2T[(nb + 1) * 20 + gid + 8] = v3;
    }
    __syncthreads();

    // ---- Layer 3 (FFMA2): K=128 (intra-warp split x2), N=64. ----
    {
        int jl = ln & 7, sg = ln >> 3;
        int j  = w * 4 + (jl >> 1);
        int kh = jl & 1;
        int s0 = sg * 4;
        u64 acc0 = 0, acc1 = 0;
        const float* Wp = W3 + kh * 64 * 64 + j;
        const float* Xp = sH2T + kh * 64 * 20 + s0;
        #pragma unroll 8
        for (int i = 0; i < 64; i++) {
            float wv = Wp[i * 64];
            double2 xv = *(const double2*)(Xp + i * 20);
            u64 wp = pack2(wv);
            ffma2(acc0, wp, d2u(xv.x));
            ffma2(acc1, wp, d2u(xv.y));
        }
        u64 r;
        r = __shfl_xor_sync(0xffffffffu, acc0, 1); fadd2(acc0, r);
        r = __shfl_xor_sync(0xffffffffu, acc1, 1); fadd2(acc1, r);
        if (kh == 0) {
            u64 bb = pack2(b3[j]);
            fadd2(acc0, bb); fadd2(acc1, bb);
            float2 f0 = unpack2(acc0), f1 = unpack2(acc1);
            *(float4*)(sH3T + j * 20 + s0) = make_float4(
                fmaxf(f0.x,0.f), fmaxf(f0.y,0.f), fmaxf(f1.x,0.f), fmaxf(f1.y,0.f));
        }
    }
    __syncthreads();

    // ---- Output: warps 0-3, 8 lanes per sample ----
    if (w < 4) {
        int s  = w * 4 + (ln >> 3);
        int q8 = ln & 7;
        float v = 0.f;
        #pragma unroll
        for (int q = 0; q < 8; q++)
            v += sH3T[(q8 * 8 + q) * 20 + s] * Wo[q8 * 8 + q];
        v += __shfl_xor_sync(0xffffffffu, v, 4, 8);
        v += __shfl_xor_sync(0xffffffffu, v, 2, 8);
        v += __shfl_xor_sync(0xffffffffu, v, 1, 8);
        if (q8 == 0 && s0blk + s < B)
            out[s0blk + s] = v + bo[0] + sBase[s];
    }
}

extern "C" void kernel_launch(void* const* d_in, const int* in_sizes, int n_in,
                              void* d_out, int out_size)
{
    (void)in_sizes; (void)n_in;
    P30 a;
    for (int i = 0; i < 30; i++) a.p[i] = d_in[i];
    prep_kernel<<<104, 256>>>((const float*)d_in[22], (const float*)d_in[24]);
    cudaFuncSetAttribute(deepfm_kernel, cudaFuncAttributeMaxDynamicSharedMemorySize, SMEM_BYTES);
    deepfm_kernel<<<NBLK, NT, SMEM_BYTES>>>(a, (float*)d_out, out_size);
}

// round 10
// speedup vs baseline: 1.0880x; 1.0770x over previous
#include <cuda_runtime.h>

#define TS   8      // samples per block
#define NT   256    // threads per block (8 warps)
#define NBLK 256    // 2048 / TS

__constant__ int c_FOFF[9] = {0,100000,150000,150010,150013,150113,150163,151163,151187};
__constant__ int c_EDIM[9] = {16,16,8,4,8,8,8,4,4};
__constant__ int c_EOFF[9] = {0,16,32,40,44,52,60,68,72};
#define NF_LAST 151192

struct P30 { const void* p[30]; };
typedef unsigned long long u64;

__device__ __forceinline__ void ffma2(u64 &d, u64 a, u64 b) {
    asm("fma.rn.f32x2 %0, %1, %2, %0;" : "+l"(d) : "l"(a), "l"(b));
}
__device__ __forceinline__ void fadd2(u64 &d, u64 a) {
    asm("add.rn.f32x2 %0, %0, %1;" : "+l"(d) : "l"(a));
}
__device__ __forceinline__ u64 pack2(float x) {
    u64 r; asm("mov.b64 %0, {%1, %1};" : "=l"(r) : "f"(x)); return r;
}
__device__ __forceinline__ float2 unpack2(u64 v) {
    float2 f; asm("mov.b64 {%0, %1}, %2;" : "=f"(f.x), "=f"(f.y) : "l"(v)); return f;
}
__device__ __forceinline__ u64 d2u(double d) { return __double_as_longlong(d); }
__device__ __forceinline__ int read_id(const void* p, int i, bool is64) {
    return is64 ? (int)((const long long*)p)[i] : ((const int*)p)[i];
}

// Activations: duplicated (v,v) u64 per sample. Row = 8 u64 (8 samples).
// K-split segments get +4 u64 pad so split-K lane groups hit disjoint banks.
// XT : 77 rows, split at 40          -> off(k,s) = k*8 + (k>=40)*4 + s
// H1 : 256 rows, segs of 64 (4-way)  -> off(i,s) = i*8 + (i>>6)*4 + s
// H2 : 128 rows, segs of 16 (8-way)  -> off(i,s) = i*8 + (i>>4)*4 + s

extern "C" __global__ void __launch_bounds__(NT, 2)
deepfm_kernel(P30 a, float* __restrict__ out, int B)
{
    __shared__ __align__(16) u64 sXTd[77 * 8 + 4];        //  4.9 KB
    __shared__ __align__(16) u64 sH1d[256 * 8 + 12];      // 16.5 KB
    __shared__ __align__(16) u64 sH2d[128 * 8 + 28];      //  8.4 KB
    __shared__ __align__(16) float sH3[64 * 12];          //  3.0 KB
    __shared__ float sBase[TS];
    __shared__ float sPrice[TS];
    __shared__ int   sIdx[TS * 9];

    const int t  = threadIdx.x;
    const int w  = t >> 5;
    const int ln = t & 31;
    const int s0blk = blockIdx.x * TS;

    // ---- input-layout detection (deterministic, data-driven) ----
    const u64* u0 = (const u64*)a.p[0];
    const bool is64 = ((u0[0] | u0[1] | u0[2] | u0[3]) < (1ULL << 20));
    const u64* u7 = (const u64*)a.p[7];
    const bool dict = (u7[0] < (1ULL << 40));

    const void* idp[9];
    #pragma unroll
    for (int f = 0; f < 7; f++) idp[f] = a.p[f];
    const float* price;
    if (dict) { idp[7] = a.p[7]; idp[8] = a.p[8]; price = (const float*)a.p[9]; }
    else      { price = (const float*)a.p[7]; idp[7] = a.p[8]; idp[8] = a.p[9]; }

    const float* emb[9];
    #pragma unroll
    for (int f = 0; f < 9; f++) emb[f] = (const float*)a.p[10 + f];
    const float* __restrict__ w_dense = (const float*)a.p[19];
    const float* __restrict__ b_dense = (const float*)a.p[20];
    const float* __restrict__ fm_v    = (const float*)a.p[21];
    const float* __restrict__ W1 = (const float*)a.p[22];
    const float* __restrict__ b1 = (const float*)a.p[23];
    const float* __restrict__ W2 = (const float*)a.p[24];
    const float* __restrict__ b2 = (const float*)a.p[25];
    const float* __restrict__ W3 = (const float*)a.p[26];
    const float* __restrict__ b3 = (const float*)a.p[27];
    const float* __restrict__ Wo = (const float*)a.p[28];
    const float* __restrict__ bo = (const float*)a.p[29];

    // ---- gather ids + price ----
    if (t < TS * 9) {
        int s = t / 9, f = t - s * 9;
        sIdx[s * 9 + f] = read_id(idp[f], s0blk + s, is64);
    }
    if (t >= 96 && t < 96 + TS) sPrice[t - 96] = price[s0blk + (t - 96)];
    __syncthreads();

    // ---- warps 0-3: FM + dense; warps 4-7: build duplicated XT ----
    if (w < 4) {
        int s = w * 2 + (ln >> 4);
        int e = ln & 15;
        float pv = sPrice[s] * 1e-3f;
        float fs = 0.f, ss = 0.f;
        #pragma unroll
        for (int f = 0; f < 9; f++) {
            int row = c_FOFF[f] + sIdx[s * 9 + f];
            float v = fm_v[row * 16 + e];
            fs += v; ss += v * v;
        }
        {
            float v = fm_v[NF_LAST * 16 + e];
            fs += pv * v; ss += pv * pv * v * v;
        }
        float val = fs * fs - ss;
        #pragma unroll
        for (int o = 8; o; o >>= 1) val += __shfl_xor_sync(0xffffffffu, val, o, 16);
        float fm = 0.5f * val;

        float dn = 0.f;
        if (e < 9)  dn = w_dense[c_FOFF[e] + sIdx[s * 9 + e]];
        if (e == 9) dn = pv * w_dense[NF_LAST];
        #pragma unroll
        for (int o = 8; o; o >>= 1) dn += __shfl_xor_sync(0xffffffffu, dn, o, 16);

        if (e == 0) sBase[s] = fm + dn + b_dense[0];
    } else {
        for (int idx = t - 128; idx < TS * 77; idx += 128) {
            int s = idx & 7, c = idx >> 3;
            float v;
            if (c == 76) v = sPrice[s];
            else {
                int f = 8;
                #pragma unroll
                for (int k = 8; k >= 1; k--) if (c < c_EOFF[k]) f = k - 1;
                v = emb[f][sIdx[s * 9 + f] * c_EDIM[f] + (c - c_EOFF[f])];
            }
            sXTd[c * 8 + (c >= 40 ? 4 : 0) + s] = pack2(v);
        }
    }
    __syncthreads();

    // ---- Layer 1: K=77 (split x2: 40/37), N=256. Warp -> 32 j. Thread: 4j x 4s. ----
    {
        int jq = ln & 7, sg = (ln >> 3) & 1, ks = ln >> 4;
        int j0 = w * 32 + jq * 4;
        int s0 = sg * 4;
        int kbeg = ks ? 40 : 0;
        int nk   = ks ? 37 : 40;
        u64 aA0=0,aA1=0,aA2=0,aA3=0, aB0=0,aB1=0,aB2=0,aB3=0;
        const float* Wp = W1 + kbeg * 256 + j0;
        const u64*   Xp = sXTd + kbeg * 8 + (ks ? 4 : 0) + s0;
        #pragma unroll 5
        for (int kk = 0; kk < nk; kk++) {
            double2 wd = *(const double2*)(Wp + kk * 256);     // (wj0,wj1),(wj2,wj3)
            double2 xa = *(const double2*)(Xp + kk * 8);       // dup s0, s0+1
            double2 xb = *(const double2*)(Xp + kk * 8 + 2);   // dup s0+2, s0+3
            u64 wA = d2u(wd.x), wB = d2u(wd.y);
            u64 x0 = d2u(xa.x), x1 = d2u(xa.y), x2 = d2u(xb.x), x3 = d2u(xb.y);
            ffma2(aA0, wA, x0); ffma2(aA1, wA, x1); ffma2(aA2, wA, x2); ffma2(aA3, wA, x3);
            ffma2(aB0, wB, x0); ffma2(aB1, wB, x1); ffma2(aB2, wB, x2); ffma2(aB3, wB, x3);
        }
        u64 r;
        r = __shfl_xor_sync(0xffffffffu, aA0, 16); fadd2(aA0, r);
        r = __shfl_xor_sync(0xffffffffu, aA1, 16); fadd2(aA1, r);
        r = __shfl_xor_sync(0xffffffffu, aA2, 16); fadd2(aA2, r);
        r = __shfl_xor_sync(0xffffffffu, aA3, 16); fadd2(aA3, r);
        r = __shfl_xor_sync(0xffffffffu, aB0, 16); fadd2(aB0, r);
        r = __shfl_xor_sync(0xffffffffu, aB1, 16); fadd2(aB1, r);
        r = __shfl_xor_sync(0xffffffffu, aB2, 16); fadd2(aB2, r);
        r = __shfl_xor_sync(0xffffffffu, aB3, 16); fadd2(aB3, r);
        if (ks == 0) {
            u64 bbA = *(const u64*)(b1 + j0);
            u64 bbB = *(const u64*)(b1 + j0 + 2);
            fadd2(aA0, bbA); fadd2(aA1, bbA); fadd2(aA2, bbA); fadd2(aA3, bbA);
            fadd2(aB0, bbB); fadd2(aB1, bbB); fadd2(aB2, bbB); fadd2(aB3, bbB);
            float2 A0 = unpack2(aA0), A1 = unpack2(aA1), A2 = unpack2(aA2), A3 = unpack2(aA3);
            float2 B0 = unpack2(aB0), B1 = unpack2(aB1), B2 = unpack2(aB2), B3 = unpack2(aB3);
            int sgh = (j0 >> 6) * 4;
            u64* r0 = sH1d + j0 * 8 + sgh + s0;
            ((double2*)r0)[0] = make_double2(__longlong_as_double(pack2(fmaxf(A0.x,0.f))),
                                             __longlong_as_double(pack2(fmaxf(A1.x,0.f))));
            ((double2*)r0)[1] = make_double2(__longlong_as_double(pack2(fmaxf(A2.x,0.f))),
                                             __longlong_as_double(pack2(fmaxf(A3.x,0.f))));
            u64* r1 = r0 + 8;
            ((double2*)r1)[0] = make_double2(__longlong_as_double(pack2(fmaxf(A0.y,0.f))),
                                             __longlong_as_double(pack2(fmaxf(A1.y,0.f))));
            ((double2*)r1)[1] = make_double2(__longlong_as_double(pack2(fmaxf(A2.y,0.f))),
                                             __longlong_as_double(pack2(fmaxf(A3.y,0.f))));
            u64* r2 = r0 + 16;
            ((double2*)r2)[0] = make_double2(__longlong_as_double(pack2(fmaxf(B0.x,0.f))),
                                             __longlong_as_double(pack2(fmaxf(B1.x,0.f))));
            ((double2*)r2)[1] = make_double2(__longlong_as_double(pack2(fmaxf(B2.x,0.f))),
                                             __longlong_as_double(pack2(fmaxf(B3.x,0.f))));
            u64* r3 = r0 + 24;
            ((double2*)r3)[0] = make_double2(__longlong_as_double(pack2(fmaxf(B0.y,0.f))),
                                             __longlong_as_double(pack2(fmaxf(B1.y,0.f))));
            ((double2*)r3)[1] = make_double2(__longlong_as_double(pack2(fmaxf(B2.y,0.f))),
                                             __longlong_as_double(pack2(fmaxf(B3.y,0.f))));
        }
    }
    __syncthreads();

    // ---- Layer 2: K=256 (split x4), N=128. Warp -> 16 j. Thread: 4j x 4s x 64k. ----
    {
        int jq = ln & 3, sg = (ln >> 2) & 1, ks = ln >> 3;
        int j0 = w * 16 + jq * 4;
        int s0 = sg * 4;
        u64 aA0=0,aA1=0,aA2=0,aA3=0, aB0=0,aB1=0,aB2=0,aB3=0;
        const float* Wp = W2 + ks * 64 * 128 + j0;
        const u64*   Xp = sH1d + ks * (64 * 8 + 4) + s0;
        #pragma unroll 8
        for (int ii = 0; ii < 64; ii++) {
            double2 wd = *(const double2*)(Wp + ii * 128);
            double2 xa = *(const double2*)(Xp + ii * 8);
            double2 xb = *(const double2*)(Xp + ii * 8 + 2);
            u64 wA = d2u(wd.x), wB = d2u(wd.y);
            u64 x0 = d2u(xa.x), x1 = d2u(xa.y), x2 = d2u(xb.x), x3 = d2u(xb.y);
            ffma2(aA0, wA, x0); ffma2(aA1, wA, x1); ffma2(aA2, wA, x2); ffma2(aA3, wA, x3);
            ffma2(aB0, wB, x0); ffma2(aB1, wB, x1); ffma2(aB2, wB, x2); ffma2(aB3, wB, x3);
        }
        u64 r;
        r = __shfl_xor_sync(0xffffffffu, aA0, 8); fadd2(aA0, r);
        r = __shfl_xor_sync(0xffffffffu, aA1, 8); fadd2(aA1, r);
        r = __shfl_xor_sync(0xffffffffu, aA2, 8); fadd2(aA2, r);
        r = __shfl_xor_sync(0xffffffffu, aA3, 8); fadd2(aA3, r);
        r = __shfl_xor_sync(0xffffffffu, aB0, 8); fadd2(aB0, r);
        r = __shfl_xor_sync(0xffffffffu, aB1, 8); fadd2(aB1, r);
        r = __shfl_xor_sync(0xffffffffu, aB2, 8); fadd2(aB2, r);
        r = __shfl_xor_sync(0xffffffffu, aB3, 8); fadd2(aB3, r);
        r = __shfl_xor_sync(0xffffffffu, aA0, 16); fadd2(aA0, r);
        r = __shfl_xor_sync(0xffffffffu, aA1, 16); fadd2(aA1, r);
        r = __shfl_xor_sync(0xffffffffu, aA2, 16); fadd2(aA2, r);
        r = __shfl_xor_sync(0xffffffffu, aA3, 16); fadd2(aA3, r);
        r = __shfl_xor_sync(0xffffffffu, aB0, 16); fadd2(aB0, r);
        r = __shfl_xor_sync(0xffffffffu, aB1, 16); fadd2(aB1, r);
        r = __shfl_xor_sync(0xffffffffu, aB2, 16); fadd2(aB2, r);
        r = __shfl_xor_sync(0xffffffffu, aB3, 16); fadd2(aB3, r);
        if (ks == 0) {
            u64 bbA = *(const u64*)(b2 + j0);
            u64 bbB = *(const u64*)(b2 + j0 + 2);
            fadd2(aA0, bbA); fadd2(aA1, bbA); fadd2(aA2, bbA); fadd2(aA3, bbA);
            fadd2(aB0, bbB); fadd2(aB1, bbB); fadd2(aB2, bbB); fadd2(aB3, bbB);
            float2 A0 = unpack2(aA0), A1 = unpack2(aA1), A2 = unpack2(aA2), A3 = unpack2(aA3);
            float2 B0 = unpack2(aB0), B1 = unpack2(aB1), B2 = unpack2(aB2), B3 = unpack2(aB3);
            int sgh = (j0 >> 4) * 4;
            u64* r0 = sH2d + j0 * 8 + sgh + s0;
            ((double2*)r0)[0] = make_double2(__longlong_as_double(pack2(fmaxf(A0.x,0.f))),
                                             __longlong_as_double(pack2(fmaxf(A1.x,0.f))));
            ((double2*)r0)[1] = make_double2(__longlong_as_double(pack2(fmaxf(A2.x,0.f))),
                                             __longlong_as_double(pack2(fmaxf(A3.x,0.f))));
            u64* r1 = r0 + 8;
            ((double2*)r1)[0] = make_double2(__longlong_as_double(pack2(fmaxf(A0.y,0.f))),
                                             __longlong_as_double(pack2(fmaxf(A1.y,0.f))));
            ((double2*)r1)[1] = make_double2(__longlong_as_double(pack2(fmaxf(A2.y,0.f))),
                                             __longlong_as_double(pack2(fmaxf(A3.y,0.f))));
            u64* r2 = r0 + 16;
            ((double2*)r2)[0] = make_double2(__longlong_as_double(pack2(fmaxf(B0.x,0.f))),
                                             __longlong_as_double(pack2(fmaxf(B1.x,0.f))));
            ((double2*)r2)[1] = make_double2(__longlong_as_double(pack2(fmaxf(B2.x,0.f))),
                                             __longlong_as_double(pack2(fmaxf(B3.x,0.f))));
            u64* r3 = r0 + 24;
            ((double2*)r3)[0] = make_double2(__longlong_as_double(pack2(fmaxf(B0.y,0.f))),
                                             __longlong_as_double(pack2(fmaxf(B1.y,0.f))));
            ((double2*)r3)[1] = make_double2(__longlong_as_double(pack2(fmaxf(B2.y,0.f))),
                                             __longlong_as_double(pack2(fmaxf(B3.y,0.f))));
        }
    }
    __syncthreads();

    // ---- Layer 3: K=128 (split x8), N=64. Warp -> 8 j. Thread: 4j x 4s x 16k. ----
    {
        int qd = ln & 1, sg = (ln >> 1) & 1, ks = ln >> 2;
        int j0 = w * 8 + qd * 4;
        int s0 = sg * 4;
        u64 aA0=0,aA1=0,aA2=0,aA3=0, aB0=0,aB1=0,aB2=0,aB3=0;
        const float* Wp = W3 + ks * 16 * 64 + j0;
        const u64*   Xp = sH2d + ks * (16 * 8 + 4) + s0;
        #pragma unroll
        for (int ii = 0; ii < 16; ii++) {
            double2 wd = *(const double2*)(Wp + ii * 64);
            double2 xa = *(const double2*)(Xp + ii * 8);
            double2 xb = *(const double2*)(Xp + ii * 8 + 2);
            u64 wA = d2u(wd.x), wB = d2u(wd.y);
            u64 x0 = d2u(xa.x), x1 = d2u(xa.y), x2 = d2u(xb.x), x3 = d2u(xb.y);
            ffma2(aA0, wA, x0); ffma2(aA1, wA, x1); ffma2(aA2, wA, x2); ffma2(aA3, wA, x3);
            ffma2(aB0, wB, x0); ffma2(aB1, wB, x1); ffma2(aB2, wB, x2); ffma2(aB3, wB, x3);
        }
        u64 r;
        #pragma unroll
        for (int o = 4; o <= 16; o <<= 1) {
            r = __shfl_xor_sync(0xffffffffu, aA0, o); fadd2(aA0, r);
            r = __shfl_xor_sync(0xffffffffu, aA1, o); fadd2(aA1, r);
            r = __shfl_xor_sync(0xffffffffu, aA2, o); fadd2(aA2, r);
            r = __shfl_xor_sync(0xffffffffu, aA3, o); fadd2(aA3, r);
            r = __shfl_xor_sync(0xffffffffu, aB0, o); fadd2(aB0, r);
            r = __shfl_xor_sync(0xffffffffu, aB1, o); fadd2(aB1, r);
            r = __shfl_xor_sync(0xffffffffu, aB2, o); fadd2(aB2, r);
            r = __shfl_xor_sync(0xffffffffu, aB3, o); fadd2(aB3, r);
        }
        if (ks == 0) {
            u64 bbA = *(const u64*)(b3 + j0);
            u64 bbB = *(const u64*)(b3 + j0 + 2);
            fadd2(aA0, bbA); fadd2(aA1, bbA); fadd2(aA2, bbA); fadd2(aA3, bbA);
            fadd2(aB0, bbB); fadd2(aB1, bbB); fadd2(aB2, bbB); fadd2(aB3, bbB);
            float2 A0 = unpack2(aA0), A1 = unpack2(aA1), A2 = unpack2(aA2), A3 = unpack2(aA3);
            float2 B0 = unpack2(aB0), B1 = unpack2(aB1), B2 = unpack2(aB2), B3 = unpack2(aB3);
            *(float4*)(sH3 + (j0    ) * 12 + s0) = make_float4(
                fmaxf(A0.x,0.f), fmaxf(A1.x,0.f), fmaxf(A2.x,0.f), fmaxf(A3.x,0.f));
            *(float4*)(sH3 + (j0 + 1) * 12 + s0) = make_float4(
                fmaxf(A0.y,0.f), fmaxf(A1.y,0.f), fmaxf(A2.y,0.f), fmaxf(A3.y,0.f));
            *(float4*)(sH3 + (j0 + 2) * 12 + s0) = make_float4(
                fmaxf(B0.x,0.f), fmaxf(B1.x,0.f), fmaxf(B2.x,0.f), fmaxf(B3.x,0.f));
            *(float4*)(sH3 + (j0 + 3) * 12 + s0) = make_float4(
                fmaxf(B0.y,0.f), fmaxf(B1.y,0.f), fmaxf(B2.y,0.f), fmaxf(B3.y,0.f));
        }
    }
    __syncthreads();

    // ---- Output: warp 0. 4 lanes per sample, each sums 16 of 64. ----
    if (w == 0) {
        int s = ln >> 2;
        int q = ln & 3;
        float v = 0.f;
        #pragma unroll
        for (int i = 0; i < 16; i++)
            v += sH3[(q * 16 + i) * 12 + s] * Wo[q * 16 + i];
        v += __shfl_xor_sync(0xffffffffu, v, 2, 4);
        v += __shfl_xor_sync(0xffffffffu, v, 1, 4);
        if (q == 0 && s0blk + s < B)
            out[s0blk + s] = v + bo[0] + sBase[s];
    }
}

extern "C" void kernel_launch(void* const* d_in, const int* in_sizes, int n_in,
                              void* d_out, int out_size)
{
    (void)in_sizes; (void)n_in;
    P30 a;
    for (int i = 0; i < 30; i++) a.p[i] = d_in[i];
    deepfm_kernel<<<NBLK, NT>>>(a, (float*)d_out, out_size);
}